// round 1
// baseline (speedup 1.0000x reference)
#include <cuda_runtime.h>

// YOLO detection decode: x (64, 255, 52, 52) f32 -> out (64, 8112, 85) f32
// c = a*85 + e (a=anchor 0..2, e=element 0..84)
// out[b, a*2704 + y*52 + x, e]:
//   e=0: (sigmoid(v)+x)*8   e=1: (sigmoid(v)+y)*8
//   e=2: exp(v)*AW[a]       e=3: exp(v)*AH[a]     e>=4: sigmoid(v)
// Block transposes a 128-row x 85-elem tile through smem:
//   reads coalesced per-channel, writes one contiguous 10880-float span.

#define G 52
#define GG 2704              // G*G
#define ROWS_PER_B 8112      // 3*GG
#define IN_PER_B 689520      // 255*GG
#define NE 85
#define TILE 128
#define THREADS 256

__constant__ float c_aw[3] = {10.0f, 16.0f, 33.0f};
__constant__ float c_ah[3] = {13.0f, 30.0f, 23.0f};

__device__ __forceinline__ float fsigmoid(float v) {
    return __fdividef(1.0f, 1.0f + __expf(-v));
}

__global__ __launch_bounds__(THREADS)
void det_decode_kernel(const float* __restrict__ x, float* __restrict__ out) {
    __shared__ float s[TILE * NE];

    const int r0 = blockIdx.x * TILE;  // first global output row of this tile

    // Phase 1: coalesced strided reads, transform, stage transposed in smem.
    // i = e*TILE + lp  -> consecutive threads share e, consecutive lp -> coalesced LDG.
    #pragma unroll 4
    for (int i = threadIdx.x; i < NE * TILE; i += THREADS) {
        const int e  = i / TILE;
        const int lp = i - e * TILE;
        const int r  = r0 + lp;             // global output row
        const int b  = r / ROWS_PER_B;
        const int n  = r - b * ROWS_PER_B;  // row within batch
        const int a  = n / GG;
        const int p  = n - a * GG;          // spatial index y*52+x

        const float v = x[b * IN_PER_B + (a * NE + e) * GG + p];

        float o;
        if (e >= 4) {
            o = fsigmoid(v);
        } else if (e == 0) {
            const int xx = p % G;
            o = (fsigmoid(v) + (float)xx) * 8.0f;
        } else if (e == 1) {
            const int yy = p / G;
            o = (fsigmoid(v) + (float)yy) * 8.0f;
        } else if (e == 2) {
            o = __expf(v) * c_aw[a];
        } else { // e == 3
            o = __expf(v) * c_ah[a];
        }
        s[lp * NE + e] = o;  // stride 85: gcd(85,32)=1 -> conflict-free
    }

    __syncthreads();

    // Phase 2: the tile's output region is one contiguous span of
    // TILE*85 = 10880 floats starting at r0*85 (multiple of 4 -> 16B aligned).
    float4* __restrict__ dst = reinterpret_cast<float4*>(out + (size_t)r0 * NE);
    const float4* __restrict__ src = reinterpret_cast<const float4*>(s);
    #pragma unroll 4
    for (int j = threadIdx.x; j < (NE * TILE) / 4; j += THREADS) {
        dst[j] = src[j];
    }
}

extern "C" void kernel_launch(void* const* d_in, const int* in_sizes, int n_in,
                              void* d_out, int out_size) {
    const float* x = (const float*)d_in[0];
    float* out = (float*)d_out;

    // total rows = 64 * 8112 = 519168 ; 519168 / 128 = 4056 blocks exactly
    const int total_rows = out_size / NE;
    const int blocks = (total_rows + TILE - 1) / TILE;
    det_decode_kernel<<<blocks, THREADS>>>(x, out);
}

// round 2
// speedup vs baseline: 1.7499x; 1.7499x over previous
#include <cuda_runtime.h>

// YOLO detection decode: x (64, 255, 52, 52) f32 -> out (64, 8112, 85) f32
// v2: TILE=104 rows (divides both GG=2704 and 8112) so each block sits inside
// one (batch, anchor) plane -> float4 loads, no per-element div chains.
// Phase 1: 85 channels x 26 float4 coalesced LDG.128, transform, transpose into smem.
// Phase 2: contiguous 8840-float span copied out as float4.

#define G 52
#define GG 2704              // G*G
#define GGV 676              // GG/4 (channel stride in float4)
#define ROWS_PER_B 8112      // 3*GG
#define IN_PER_B 689520      // 255*GG
#define NE 85
#define TILE 104
#define QV 26                // TILE/4
#define NV (NE * QV)         // 2210 float4 per tile
#define THREADS 256

__constant__ float c_aw[3] = {10.0f, 16.0f, 33.0f};
__constant__ float c_ah[3] = {13.0f, 30.0f, 23.0f};

__device__ __forceinline__ float fsigmoid(float v) {
    return __fdividef(1.0f, 1.0f + __expf(-v));
}

__global__ __launch_bounds__(THREADS)
void det_decode_kernel(const float* __restrict__ x, float* __restrict__ out) {
    __shared__ float s[TILE * NE];   // 34,680 B

    // Tile -> (b, a, p0). tiles/anchor = 26, tiles/batch = 78.
    const int t   = blockIdx.x;
    const int b   = t / 78;
    const int rem = t - b * 78;
    const int a   = rem / 26;
    const int pt  = rem - a * 26;
    const int p0  = pt * TILE;       // spatial offset within the (b,a) plane

    const float4* __restrict__ src = reinterpret_cast<const float4*>(
        x + (size_t)b * IN_PER_B + (size_t)(a * NE) * GG + p0);

    const float aw = c_aw[a];
    const float ah = c_ah[a];

    // Phase 1: load-transform-stage.
    #pragma unroll 4
    for (int j = threadIdx.x; j < NV; j += THREADS) {
        const int e = j / QV;            // channel 0..84
        const int q = j - e * QV;        // float4 index within channel
        const float4 v = src[e * GGV + q];
        const int lp = q * 4;            // local row of component .x

        float o0, o1, o2, o3;
        if (e >= 4) {
            o0 = fsigmoid(v.x); o1 = fsigmoid(v.y);
            o2 = fsigmoid(v.z); o3 = fsigmoid(v.w);
        } else if (e == 0) {
            const int p = p0 + lp;
            o0 = (fsigmoid(v.x) + (float)((p    ) % G)) * 8.0f;
            o1 = (fsigmoid(v.y) + (float)((p + 1) % G)) * 8.0f;
            o2 = (fsigmoid(v.z) + (float)((p + 2) % G)) * 8.0f;
            o3 = (fsigmoid(v.w) + (float)((p + 3) % G)) * 8.0f;
        } else if (e == 1) {
            const int p = p0 + lp;
            o0 = (fsigmoid(v.x) + (float)((p    ) / G)) * 8.0f;
            o1 = (fsigmoid(v.y) + (float)((p + 1) / G)) * 8.0f;
            o2 = (fsigmoid(v.z) + (float)((p + 2) / G)) * 8.0f;
            o3 = (fsigmoid(v.w) + (float)((p + 3) / G)) * 8.0f;
        } else if (e == 2) {
            o0 = __expf(v.x) * aw; o1 = __expf(v.y) * aw;
            o2 = __expf(v.z) * aw; o3 = __expf(v.w) * aw;
        } else { // e == 3
            o0 = __expf(v.x) * ah; o1 = __expf(v.y) * ah;
            o2 = __expf(v.z) * ah; o3 = __expf(v.w) * ah;
        }
        // transpose into smem (stride NE between rows)
        float* sp = s + lp * NE + e;
        sp[0 * NE] = o0; sp[1 * NE] = o1; sp[2 * NE] = o2; sp[3 * NE] = o3;
    }

    __syncthreads();

    // Phase 2: tile's output is one contiguous span of TILE*NE = 8840 floats.
    float4* __restrict__ dst =
        reinterpret_cast<float4*>(out + (size_t)t * (TILE * NE));
    const float4* __restrict__ ss = reinterpret_cast<const float4*>(s);
    #pragma unroll 4
    for (int j = threadIdx.x; j < NV; j += THREADS) {
        dst[j] = ss[j];
    }
}

extern "C" void kernel_launch(void* const* d_in, const int* in_sizes, int n_in,
                              void* d_out, int out_size) {
    const float* x = (const float*)d_in[0];
    float* out = (float*)d_out;
    const int blocks = out_size / (TILE * NE);   // 519168*85 / 8840 = 4992
    det_decode_kernel<<<blocks, THREADS>>>(x, out);
}

// round 3
// speedup vs baseline: 2.2008x; 1.2576x over previous
#include <cuda_runtime.h>

// YOLO detection decode: x (64, 255, 52, 52) f32 -> out (64, 8112, 85) f32
// v3: TILE=52 (divides GG) -> smem 17.7KB -> 8 blocks/SM, 100% theoretical occ.
// Phase 1: per channel, 13 coalesced float4 LDG, transform, transpose into smem.
// Phase 2: contiguous 4420-float span stored as float4 (streaming).

#define G 52
#define GG 2704              // G*G
#define GGV 676              // GG/4 (channel stride in float4)
#define IN_PER_B 689520      // 255*GG
#define NE 85
#define TILE 52
#define QV 13                // TILE/4
#define NV (NE * QV)         // 1105 float4 per tile
#define TILES_PER_PLANE 52   // GG / TILE
#define THREADS 256

__constant__ float c_aw[3] = {10.0f, 16.0f, 33.0f};
__constant__ float c_ah[3] = {13.0f, 30.0f, 23.0f};

__device__ __forceinline__ float fsigmoid(float v) {
    return __fdividef(1.0f, 1.0f + __expf(-v));
}

__global__ __launch_bounds__(THREADS)
void det_decode_kernel(const float* __restrict__ x, float* __restrict__ out) {
    __shared__ float s[TILE * NE];   // 17,680 B

    // Tile -> (b, a, p0). tiles/anchor = 52, tiles/batch = 156.
    const int t   = blockIdx.x;
    const int b   = t / 156;
    const int rem = t - b * 156;
    const int a   = rem / TILES_PER_PLANE;
    const int pt  = rem - a * TILES_PER_PLANE;
    const int p0  = pt * TILE;       // spatial offset within the (b,a) plane

    const float4* __restrict__ src = reinterpret_cast<const float4*>(
        x + (size_t)b * IN_PER_B + (size_t)(a * NE) * GG + p0);

    const float aw = c_aw[a];
    const float ah = c_ah[a];

    // Phase 1: load-transform-stage.
    #pragma unroll 4
    for (int j = threadIdx.x; j < NV; j += THREADS) {
        const int e = j / QV;            // channel 0..84
        const int q = j - e * QV;        // float4 index within channel
        const float4 v = __ldcs(src + e * GGV + q);
        const int lp = q * 4;            // local row of component .x

        float o0, o1, o2, o3;
        if (e >= 4) {
            o0 = fsigmoid(v.x); o1 = fsigmoid(v.y);
            o2 = fsigmoid(v.z); o3 = fsigmoid(v.w);
        } else if (e == 0) {
            const int p = p0 + lp;
            o0 = (fsigmoid(v.x) + (float)((p    ) % G)) * 8.0f;
            o1 = (fsigmoid(v.y) + (float)((p + 1) % G)) * 8.0f;
            o2 = (fsigmoid(v.z) + (float)((p + 2) % G)) * 8.0f;
            o3 = (fsigmoid(v.w) + (float)((p + 3) % G)) * 8.0f;
        } else if (e == 1) {
            const int p = p0 + lp;
            o0 = (fsigmoid(v.x) + (float)((p    ) / G)) * 8.0f;
            o1 = (fsigmoid(v.y) + (float)((p + 1) / G)) * 8.0f;
            o2 = (fsigmoid(v.z) + (float)((p + 2) / G)) * 8.0f;
            o3 = (fsigmoid(v.w) + (float)((p + 3) / G)) * 8.0f;
        } else if (e == 2) {
            o0 = __expf(v.x) * aw; o1 = __expf(v.y) * aw;
            o2 = __expf(v.z) * aw; o3 = __expf(v.w) * aw;
        } else { // e == 3
            o0 = __expf(v.x) * ah; o1 = __expf(v.y) * ah;
            o2 = __expf(v.z) * ah; o3 = __expf(v.w) * ah;
        }
        // transpose into smem (row stride NE)
        float* sp = s + lp * NE + e;
        sp[0 * NE] = o0; sp[1 * NE] = o1; sp[2 * NE] = o2; sp[3 * NE] = o3;
    }

    __syncthreads();

    // Phase 2: tile's output is one contiguous span of TILE*NE = 4420 floats.
    float4* __restrict__ dst =
        reinterpret_cast<float4*>(out + (size_t)t * (TILE * NE));
    const float4* __restrict__ ss = reinterpret_cast<const float4*>(s);
    #pragma unroll 4
    for (int j = threadIdx.x; j < NV; j += THREADS) {
        __stcs(dst + j, ss[j]);
    }
}

extern "C" void kernel_launch(void* const* d_in, const int* in_sizes, int n_in,
                              void* d_out, int out_size) {
    const float* x = (const float*)d_in[0];
    float* out = (float*)d_out;
    const int blocks = out_size / (TILE * NE);   // 9984
    det_decode_kernel<<<blocks, THREADS>>>(x, out);
}